// round 14
// baseline (speedup 1.0000x reference)
#include <cuda_runtime.h>
#include <cuda_fp16.h>
#include <stdint.h>

// Problem constants
#define N_SRC0 200000
#define N_DST0 50000
#define N_DST1 10000
#define NE0    800000
#define NE1    160000
#define DIM    256
#define NBASE  4
#define BD     64
#define NPAIR  5000
#define NPTOT  (2 * NPAIR)

#define SCAN_CHUNK 4096
#define NBLK0 ((N_DST0 + SCAN_CHUNK - 1) / SCAN_CHUNK)   // 13
#define NBLK1 ((N_DST1 + SCAN_CHUNK - 1) / SCAN_CHUNK)   // 3
#define NBLKS (NBLK0 + NBLK1)                            // 16

#define NEDGE_BLK ((NE0 + NE1 + 255) / 256)              // 3750
#define NCVT_TOT  ((N_SRC0 * (DIM / 16)) / 256)          // 12500 (16 floats/thr)
#define NCVT_H    (NCVT_TOT / 2)                         // 6250

// ---------------------------------------------------------------------------
// Scratch
// ---------------------------------------------------------------------------
__device__ __align__(16) __half g_agg0h[(size_t)N_DST0 * DIM];
__device__ __align__(16) __half g_agg1h[(size_t)N_DST1 * DIM];
__device__ __align__(16) __half g_h0h[(size_t)N_DST0 * DIM];
__device__ float  g_h1[(size_t)N_DST1 * DIM];
__device__ __align__(16) __half g_xh[(size_t)N_SRC0 * DIM];

// fp16 weights (converted once per call in zero_kernel)
__device__ __align__(16) __half g_lw0h[DIM * DIM];
__device__ __align__(16) __half g_lw1h[DIM * DIM];
__device__ __align__(16) __half g_w0h[NBASE * BD * BD];
__device__ __align__(16) __half g_w1h[NBASE * BD * BD];

__device__ __align__(16) int g_cnt0[N_DST0];
__device__ __align__(16) int g_cnt1[N_DST1];
__device__ __align__(16) int g_rowptr0[N_DST0 + 1];
__device__ __align__(16) int g_rowptr1[N_DST1 + 1];
__device__ __align__(16) int g_cur0[N_DST0];
__device__ __align__(16) int g_cur1[N_DST1];
__device__ int g_esrc0[NE0];
__device__ int g_esrc1[NE1];
__device__ int g_part[NBLKS];
__device__ int g_flag[NBLKS];

// ---------------------------------------------------------------------------
// cp.async helpers
// ---------------------------------------------------------------------------
__device__ __forceinline__ void cp16(uint32_t dst, const void* src, int bytes) {
    asm volatile("cp.async.cg.shared.global [%0], [%1], 16, %2;\n"
                 :: "r"(dst), "l"(src), "r"(bytes));
}
__device__ __forceinline__ void cp_commit() {
    asm volatile("cp.async.commit_group;\n");
}
template <int N>
__device__ __forceinline__ void cp_wait() {
    asm volatile("cp.async.wait_group %0;\n" :: "n"(N));
}

// ---------------------------------------------------------------------------
// Convert helper: one block converts 256*16 floats (4 LDG.128 + 2 STG.128 /thr)
// ---------------------------------------------------------------------------
__device__ __forceinline__ void convert_block(const float* __restrict__ x,
                                              size_t blk) {
    size_t i = blk * 256 + threadIdx.x;
    const float4* x4 = (const float4*)x;
    float4 a = x4[4 * i];
    float4 b = x4[4 * i + 1];
    float4 c = x4[4 * i + 2];
    float4 d = x4[4 * i + 3];
    __half2 h0 = __floats2half2_rn(a.x, a.y);
    __half2 h1 = __floats2half2_rn(a.z, a.w);
    __half2 h2 = __floats2half2_rn(b.x, b.y);
    __half2 h3 = __floats2half2_rn(b.z, b.w);
    __half2 h4 = __floats2half2_rn(c.x, c.y);
    __half2 h5 = __floats2half2_rn(c.z, c.w);
    __half2 h6 = __floats2half2_rn(d.x, d.y);
    __half2 h7 = __floats2half2_rn(d.z, d.w);
    uint4 o0, o1;
    o0.x = *(uint32_t*)&h0; o0.y = *(uint32_t*)&h1;
    o0.z = *(uint32_t*)&h2; o0.w = *(uint32_t*)&h3;
    o1.x = *(uint32_t*)&h4; o1.y = *(uint32_t*)&h5;
    o1.z = *(uint32_t*)&h6; o1.w = *(uint32_t*)&h7;
    ((uint4*)g_xh)[2 * i]     = o0;
    ((uint4*)g_xh)[2 * i + 1] = o1;
}

// ---------------------------------------------------------------------------
// Zero counters + scan flags, convert weights to fp16
// ---------------------------------------------------------------------------
__global__ void zero_kernel(const float* __restrict__ loop0,
                            const float* __restrict__ W0,
                            const float* __restrict__ loop1,
                            const float* __restrict__ W1) {
    int stride = gridDim.x * blockDim.x;
    int i0 = blockIdx.x * blockDim.x + threadIdx.x;
    for (int i = i0; i < N_DST0; i += stride) g_cnt0[i] = 0;
    for (int i = i0; i < N_DST1; i += stride) g_cnt1[i] = 0;
    if (i0 < NBLKS) g_flag[i0] = 0;
    for (int i = i0; i < DIM * DIM / 2; i += stride) {
        float2 v = ((const float2*)loop0)[i];
        ((__half2*)g_lw0h)[i] = __floats2half2_rn(v.x, v.y);
        float2 u = ((const float2*)loop1)[i];
        ((__half2*)g_lw1h)[i] = __floats2half2_rn(u.x, u.y);
    }
    for (int i = i0; i < NBASE * BD * BD / 2; i += stride) {
        float2 v = ((const float2*)W0)[i];
        ((__half2*)g_w0h)[i] = __floats2half2_rn(v.x, v.y);
        float2 u = ((const float2*)W1)[i];
        ((__half2*)g_w1h)[i] = __floats2half2_rn(u.x, u.y);
    }
}

// ---------------------------------------------------------------------------
// Fused: edge counting + first half of x conversion
// ---------------------------------------------------------------------------
__global__ __launch_bounds__(256) void count_convert_kernel(
    const float* __restrict__ x,
    const int*   __restrict__ dst0,
    const int*   __restrict__ dst1)
{
    int bid = blockIdx.x;
    if (bid < NEDGE_BLK) {
        int e = bid * 256 + threadIdx.x;
        if (e < NE0)            atomicAdd(&g_cnt0[dst0[e]], 1);
        else if (e < NE0 + NE1) atomicAdd(&g_cnt1[dst1[e - NE0]], 1);
    } else {
        convert_block(x, (size_t)(bid - NEDGE_BLK));
    }
}

// ---------------------------------------------------------------------------
// Single-launch scan with decoupled lookback (16 blocks).
// ---------------------------------------------------------------------------
__global__ __launch_bounds__(512) void scan_kernel() {
    const int* cnt; int* rowptr; int* cur; int n, nblk, b, gb, segbase;
    gb = blockIdx.x;
    if (gb < NBLK0) {
        cnt = g_cnt0; rowptr = g_rowptr0; cur = g_cur0;
        n = N_DST0; nblk = NBLK0; b = gb; segbase = 0;
    } else {
        cnt = g_cnt1; rowptr = g_rowptr1; cur = g_cur1;
        n = N_DST1; nblk = NBLK1; b = gb - NBLK0; segbase = NBLK0;
    }

    __shared__ int wsum[16];
    __shared__ int s_off;
    const int tid  = threadIdx.x;
    const int lane = tid & 31;
    const int wid  = tid >> 5;
    const int idx0 = b * SCAN_CHUNK + tid * 8;

    int v[8];
    if (idx0 + 8 <= n) {
        int4 a = *(const int4*)(cnt + idx0);
        int4 c = *(const int4*)(cnt + idx0 + 4);
        v[0]=a.x; v[1]=a.y; v[2]=a.z; v[3]=a.w;
        v[4]=c.x; v[5]=c.y; v[6]=c.z; v[7]=c.w;
    } else {
        #pragma unroll
        for (int j = 0; j < 8; ++j) v[j] = (idx0 + j < n) ? cnt[idx0 + j] : 0;
    }
    int incl[8]; int tot = 0;
    #pragma unroll
    for (int j = 0; j < 8; ++j) { tot += v[j]; incl[j] = tot; }

    int wincl = tot;
    #pragma unroll
    for (int o = 1; o < 32; o <<= 1) {
        int t = __shfl_up_sync(0xFFFFFFFFu, wincl, o);
        if (lane >= o) wincl += t;
    }
    if (lane == 31) wsum[wid] = wincl;
    __syncthreads();
    if (tid == 0) {
        int running = 0;
        #pragma unroll
        for (int w = 0; w < 16; ++w) { int t = wsum[w]; wsum[w] = running; running += t; }
        g_part[gb] = running;
        __threadfence();
        atomicExch(&g_flag[gb], 1);
        int off = 0;
        for (int k = segbase; k < gb; ++k) {
            while (atomicAdd(&g_flag[k], 0) == 0) { }
            off += *((volatile int*)&g_part[k]);
        }
        s_off = off;
    }
    __syncthreads();

    int off = s_off;
    int myexcl = off + wsum[wid] + (wincl - tot);
    if (idx0 + 8 <= n) {
        int4 r0 = make_int4(myexcl + incl[0]-v[0], myexcl + incl[1]-v[1],
                            myexcl + incl[2]-v[2], myexcl + incl[3]-v[3]);
        int4 r1 = make_int4(myexcl + incl[4]-v[4], myexcl + incl[5]-v[5],
                            myexcl + incl[6]-v[6], myexcl + incl[7]-v[7]);
        *(int4*)(rowptr + idx0)     = r0;
        *(int4*)(rowptr + idx0 + 4) = r1;
        *(int4*)(cur + idx0)        = r0;
        *(int4*)(cur + idx0 + 4)    = r1;
    } else {
        #pragma unroll
        for (int j = 0; j < 8; ++j)
            if (idx0 + j < n) {
                int e = myexcl + incl[j] - v[j];
                rowptr[idx0 + j] = e;
                cur[idx0 + j] = e;
            }
    }
    if (b == nblk - 1 && tid == 0) rowptr[n] = off + g_part[gb];
}

// ---------------------------------------------------------------------------
// Fused: CSR fill + second half of x conversion
// ---------------------------------------------------------------------------
__global__ __launch_bounds__(256) void fill_convert_kernel(
    const float* __restrict__ x,
    const int* __restrict__ src0, const int* __restrict__ dst0,
    const int* __restrict__ src1, const int* __restrict__ dst1)
{
    int bid = blockIdx.x;
    if (bid < NEDGE_BLK) {
        int e = bid * 256 + threadIdx.x;
        if (e < NE0) {
            int p = atomicAdd(&g_cur0[dst0[e]], 1);
            g_esrc0[p] = src0[e];
        } else if (e < NE0 + NE1) {
            int e1 = e - NE0;
            int p = atomicAdd(&g_cur1[dst1[e1]], 1);
            g_esrc1[p] = src1[e1];
        }
    } else {
        convert_block(x, (size_t)(bid - NEDGE_BLK) + NCVT_H);
    }
}

// ---------------------------------------------------------------------------
// Pull gather (fp16 -> fp16 agg, fp32 accumulation). 32 threads/row,
// 8-edge unroll for MLP.
// ---------------------------------------------------------------------------
template <int WHICH>
__global__ __launch_bounds__(128) void gather_kernel() {
    const __half* feat = WHICH ? g_h0h : g_xh;
    __half* agg        = WHICH ? g_agg1h : g_agg0h;
    const int* rowptr  = WHICH ? g_rowptr1 : g_rowptr0;
    const int* esrc    = WHICH ? g_esrc1 : g_esrc0;
    const int ndst     = WHICH ? N_DST1 : N_DST0;

    int d = blockIdx.x * 4 + (threadIdx.x >> 5);
    int lane = threadIdx.x & 31;
    if (d >= ndst) return;

    int beg = rowptr[d], end = rowptr[d + 1];
    float a0=0.f,a1=0.f,a2=0.f,a3=0.f,a4=0.f,a5=0.f,a6=0.f,a7=0.f;
    const uint4* f16 = (const uint4*)feat;

    #define ACCUM(v) do {                                           \
        float2 _f;                                                  \
        _f = __half22float2(*(__half2*)&(v).x); a0 += _f.x; a1 += _f.y; \
        _f = __half22float2(*(__half2*)&(v).y); a2 += _f.x; a3 += _f.y; \
        _f = __half22float2(*(__half2*)&(v).z); a4 += _f.x; a5 += _f.y; \
        _f = __half22float2(*(__half2*)&(v).w); a6 += _f.x; a7 += _f.y; \
    } while (0)

    int i = beg;
    for (; i + 7 < end; i += 8) {
        int s[8];
        #pragma unroll
        for (int j = 0; j < 8; ++j) s[j] = esrc[i + j];
        uint4 v[8];
        #pragma unroll
        for (int j = 0; j < 8; ++j) v[j] = f16[(size_t)s[j] * 32 + lane];
        #pragma unroll
        for (int j = 0; j < 8; ++j) ACCUM(v[j]);
    }
    for (; i + 3 < end; i += 4) {
        int s0 = esrc[i], s1 = esrc[i + 1], s2 = esrc[i + 2], s3 = esrc[i + 3];
        uint4 v0 = f16[(size_t)s0 * 32 + lane];
        uint4 v1 = f16[(size_t)s1 * 32 + lane];
        uint4 v2 = f16[(size_t)s2 * 32 + lane];
        uint4 v3 = f16[(size_t)s3 * 32 + lane];
        ACCUM(v0); ACCUM(v1); ACCUM(v2); ACCUM(v3);
    }
    for (; i < end; ++i) {
        int s0 = esrc[i];
        uint4 v0 = f16[(size_t)s0 * 32 + lane];
        ACCUM(v0);
    }
    #undef ACCUM

    __half2 o0 = __floats2half2_rn(a0, a1);
    __half2 o1 = __floats2half2_rn(a2, a3);
    __half2 o2 = __floats2half2_rn(a4, a5);
    __half2 o3 = __floats2half2_rn(a6, a7);
    uint4 ov;
    ov.x = *(uint32_t*)&o0; ov.y = *(uint32_t*)&o1;
    ov.z = *(uint32_t*)&o2; ov.w = *(uint32_t*)&o3;
    ((uint4*)agg)[(size_t)d * 32 + lane] = ov;
}

// ---------------------------------------------------------------------------
// fp16 tensor-core fused layer GEMM, double-buffered cp.async pipeline.
// ---------------------------------------------------------------------------
__device__ __forceinline__ __half2 f2h2(float a, float b) {
    return __floats2half2_rn(a, b);
}

template <int LAYER>
__global__ __launch_bounds__(256) void layer_kernel(
    const float* __restrict__ bias,   // [256] fp32
    float*       __restrict__ out2,   // layer1: mirror to d_out region
    int M)
{
    const __half* aggh = (LAYER == 0) ? g_agg0h : g_agg1h;
    const __half* xdh  = (LAYER == 0) ? g_xh   : g_h0h;
    const __half* lw   = (LAYER == 0) ? g_lw0h : g_lw1h;
    const __half* wbd  = (LAYER == 0) ? g_w0h  : g_w1h;

    __shared__ __half As[2][128][40];
    __shared__ __half Bs[2][32][72];

    const int cb  = blockIdx.x;
    const int r0  = blockIdx.y * 128;
    const int tid = threadIdx.x;
    const int lane = tid & 31;
    const int w   = tid >> 5;
    const int wm  = w & 3;
    const int wn  = w >> 2;
    const int t4  = lane >> 2;
    const int tc  = lane & 3;

    const int arow0 = tid >> 2,         aq0 = tid & 3;
    const int arow1 = (tid + 256) >> 2, aq1 = (tid + 256) & 3;
    const int bk = tid >> 3, bq = tid & 7;
    uint32_t asA[2], asA2[2], asB[2];
    #pragma unroll
    for (int s = 0; s < 2; ++s) {
        asA[s]  = (uint32_t)__cvta_generic_to_shared(&As[s][arow0][aq0 * 8]);
        asA2[s] = (uint32_t)__cvta_generic_to_shared(&As[s][arow1][aq1 * 8]);
        asB[s]  = (uint32_t)__cvta_generic_to_shared(&Bs[s][bk][bq * 8]);
    }

    float acc[2][4][4];
    #pragma unroll
    for (int mt = 0; mt < 2; ++mt)
        #pragma unroll
        for (int nt = 0; nt < 4; ++nt)
            #pragma unroll
            for (int i = 0; i < 4; ++i) acc[mt][nt][i] = 0.f;

    auto issue = [&](int ch, int buf) {
        const int akbase = (ch < 8) ? ch * 32 : cb * 64 + (ch - 8) * 32;
        const __half* amat = (ch < 8) ? xdh : aggh;
        int r = r0 + arow0;
        cp16(asA[buf],
             amat + (size_t)(r < M ? r : 0) * DIM + akbase + aq0 * 8,
             r < M ? 16 : 0);
        r = r0 + arow1;
        cp16(asA2[buf],
             amat + (size_t)(r < M ? r : 0) * DIM + akbase + aq1 * 8,
             r < M ? 16 : 0);
        const __half* bsrc = (ch < 8)
            ? lw + (size_t)(ch * 32 + bk) * DIM + cb * 64 + bq * 8
            : wbd + (size_t)cb * BD * BD + (size_t)((ch - 8) * 32 + bk) * BD + bq * 8;
        cp16(asB[buf], bsrc, 16);
        cp_commit();
    };

    issue(0, 0);
    for (int ch = 0; ch < 10; ++ch) {
        const int buf = ch & 1;
        if (ch < 9) issue(ch + 1, buf ^ 1);
        if (ch < 9) cp_wait<1>(); else cp_wait<0>();
        __syncthreads();

        const __half (*A)[40] = As[buf];
        const __half (*B)[72] = Bs[buf];
        #pragma unroll
        for (int ks = 0; ks < 2; ++ks) {
            const int kb = ks * 16;
            uint32_t a[2][4];
            #pragma unroll
            for (int mt = 0; mt < 2; ++mt) {
                int mrow = wm * 32 + mt * 16 + t4;
                a[mt][0] = *(const uint32_t*)&A[mrow][kb + 2 * tc];
                a[mt][1] = *(const uint32_t*)&A[mrow + 8][kb + 2 * tc];
                a[mt][2] = *(const uint32_t*)&A[mrow][kb + 2 * tc + 8];
                a[mt][3] = *(const uint32_t*)&A[mrow + 8][kb + 2 * tc + 8];
            }
            #pragma unroll
            for (int nt = 0; nt < 4; ++nt) {
                int ncol = wn * 32 + nt * 8 + t4;
                uint32_t b0 = (uint32_t)*(const uint16_t*)&B[kb + 2 * tc][ncol]
                            | ((uint32_t)*(const uint16_t*)&B[kb + 2 * tc + 1][ncol] << 16);
                uint32_t b1 = (uint32_t)*(const uint16_t*)&B[kb + 2 * tc + 8][ncol]
                            | ((uint32_t)*(const uint16_t*)&B[kb + 2 * tc + 9][ncol] << 16);
                #pragma unroll
                for (int mt = 0; mt < 2; ++mt) {
                    asm volatile(
                        "mma.sync.aligned.m16n8k16.row.col.f32.f16.f16.f32 "
                        "{%0,%1,%2,%3}, {%4,%5,%6,%7}, {%8,%9}, {%0,%1,%2,%3};\n"
                        : "+f"(acc[mt][nt][0]), "+f"(acc[mt][nt][1]),
                          "+f"(acc[mt][nt][2]), "+f"(acc[mt][nt][3])
                        : "r"(a[mt][0]), "r"(a[mt][1]), "r"(a[mt][2]), "r"(a[mt][3]),
                          "r"(b0), "r"(b1));
                }
            }
        }
        __syncthreads();
    }

    #pragma unroll
    for (int nt = 0; nt < 4; ++nt) {
        int c = cb * 64 + wn * 32 + nt * 8 + 2 * tc;
        float2 bb = *(const float2*)(bias + c);
        #pragma unroll
        for (int mt = 0; mt < 2; ++mt) {
            int r = r0 + wm * 32 + mt * 16 + t4;
            float ox0 = fmaxf(acc[mt][nt][0] + bb.x, 0.f);
            float oy0 = fmaxf(acc[mt][nt][1] + bb.y, 0.f);
            float ox1 = fmaxf(acc[mt][nt][2] + bb.x, 0.f);
            float oy1 = fmaxf(acc[mt][nt][3] + bb.y, 0.f);
            if (LAYER == 0) {
                if (r < M)
                    *(__half2*)(g_h0h + (size_t)r * DIM + c) = f2h2(ox0, oy0);
                if (r + 8 < M)
                    *(__half2*)(g_h0h + (size_t)(r + 8) * DIM + c) = f2h2(ox1, oy1);
            } else {
                if (r < M) {
                    float2 o = make_float2(ox0, oy0);
                    *(float2*)(g_h1 + (size_t)r * DIM + c) = o;
                    *(float2*)(out2 + (size_t)r * DIM + c) = o;
                }
                if (r + 8 < M) {
                    float2 o = make_float2(ox1, oy1);
                    *(float2*)(g_h1 + (size_t)(r + 8) * DIM + c) = o;
                    *(float2*)(out2 + (size_t)(r + 8) * DIM + c) = o;
                }
            }
        }
    }
}

// ---------------------------------------------------------------------------
// Link predictor, batched: 32 pairs per 128-thread block.
// ---------------------------------------------------------------------------
#define PPB 32
__global__ __launch_bounds__(128) void pred_kernel(
    const int*   __restrict__ ps, const int* __restrict__ pd,
    const int*   __restrict__ ns, const int* __restrict__ nd,
    const float* __restrict__ pw1,
    const float* __restrict__ pb1,
    const float* __restrict__ pw2,
    const float* __restrict__ pb2,
    float*       __restrict__ out)
{
    const float* h = g_h1;
    __shared__ float es[PPB][256];
    __shared__ int   sa[PPB], sb[PPB];
    __shared__ float s_part[4][PPB];

    int tid  = threadIdx.x;
    int lane = tid & 31;
    int wid  = tid >> 5;
    int pbase = blockIdx.x * PPB;

    if (tid < PPB) {
        int P = pbase + tid;
        int a = 0, b = 0;
        if (P < NPTOT) {
            if (P < NPAIR) { a = ps[P]; b = pd[P]; }
            else           { a = ns[P - NPAIR]; b = nd[P - NPAIR]; }
        }
        sa[tid] = a; sb[tid] = b;
    }
    __syncthreads();

    #pragma unroll 4
    for (int p = 0; p < PPB; ++p) {
        int a = sa[p], b = sb[p];
        es[p][tid]       = h[(size_t)a * DIM + tid]       * h[(size_t)b * DIM + tid];
        es[p][tid + 128] = h[(size_t)a * DIM + 128 + tid] * h[(size_t)b * DIM + 128 + tid];
    }
    __syncthreads();

    float acc[PPB];
    #pragma unroll
    for (int p = 0; p < PPB; ++p) acc[p] = 0.f;

    for (int j = 0; j < 256; j += 4) {
        float w0 = pw1[(j + 0) * 128 + tid];
        float w1 = pw1[(j + 1) * 128 + tid];
        float w2 = pw1[(j + 2) * 128 + tid];
        float w3 = pw1[(j + 3) * 128 + tid];
        #pragma unroll
        for (int p = 0; p < PPB; ++p) {
            float4 e4 = *(const float4*)&es[p][j];
            acc[p] += e4.x * w0 + e4.y * w1 + e4.z * w2 + e4.w * w3;
        }
    }

    float pb  = pb1[tid];
    float w2v = pw2[tid];
    #pragma unroll
    for (int p = 0; p < PPB; ++p) {
        float v = fmaxf(acc[p] + pb, 0.f) * w2v;
        #pragma unroll
        for (int o = 16; o; o >>= 1) v += __shfl_xor_sync(0xFFFFFFFFu, v, o);
        if (lane == 0) s_part[wid][p] = v;
    }
    __syncthreads();
    if (tid < PPB) {
        int P = pbase + tid;
        if (P < NPTOT)
            out[P] = s_part[0][tid] + s_part[1][tid] + s_part[2][tid] + s_part[3][tid]
                   + pb2[0];
    }
}

// ---------------------------------------------------------------------------
// Launch
// ---------------------------------------------------------------------------
extern "C" void kernel_launch(void* const* d_in, const int* in_sizes, int n_in,
                              void* d_out, int out_size)
{
    const float* x     = (const float*)d_in[0];
    const int*   src0  = (const int*)d_in[1];
    const int*   dst0  = (const int*)d_in[2];
    const int*   src1  = (const int*)d_in[3];
    const int*   dst1  = (const int*)d_in[4];
    const int*   psrc  = (const int*)d_in[5];
    const int*   pdst  = (const int*)d_in[6];
    const int*   nsrc  = (const int*)d_in[7];
    const int*   ndst  = (const int*)d_in[8];
    const float* W0    = (const float*)d_in[9];
    const float* loop0 = (const float*)d_in[10];
    const float* b0    = (const float*)d_in[11];
    const float* W1    = (const float*)d_in[12];
    const float* loop1 = (const float*)d_in[13];
    const float* b1    = (const float*)d_in[14];
    const float* pw1   = (const float*)d_in[15];
    const float* pb1   = (const float*)d_in[16];
    const float* pw2   = (const float*)d_in[17];
    const float* pb2   = (const float*)d_in[18];
    float*       out   = (float*)d_out;

    zero_kernel<<<256, 256>>>(loop0, W0, loop1, W1);
    count_convert_kernel<<<NEDGE_BLK + NCVT_H, 256>>>(x, dst0, dst1);
    scan_kernel<<<NBLKS, 512>>>();
    fill_convert_kernel<<<NEDGE_BLK + (NCVT_TOT - NCVT_H), 256>>>(
        x, src0, dst0, src1, dst1);

    gather_kernel<0><<<(N_DST0 + 3) / 4, 128>>>();
    {
        dim3 grid(NBASE, (N_DST0 + 127) / 128);
        layer_kernel<0><<<grid, 256>>>(b0, nullptr, N_DST0);
    }

    gather_kernel<1><<<(N_DST1 + 3) / 4, 128>>>();
    {
        dim3 grid(NBASE, (N_DST1 + 127) / 128);
        layer_kernel<1><<<grid, 256>>>(b1, out + NPTOT, N_DST1);
    }

    pred_kernel<<<(NPTOT + PPB - 1) / PPB, 128>>>(psrc, pdst, nsrc, ndst,
                                                  pw1, pb1, pw2, pb2, out);
}

// round 15
// speedup vs baseline: 1.0321x; 1.0321x over previous
#include <cuda_runtime.h>
#include <cuda_fp16.h>
#include <stdint.h>

// Problem constants
#define N_SRC0 200000
#define N_DST0 50000
#define N_DST1 10000
#define NE0    800000
#define NE1    160000
#define DIM    256
#define NBASE  4
#define BD     64
#define NPAIR  5000
#define NPTOT  (2 * NPAIR)

#define SCAN_CHUNK 4096
#define NBLK0 ((N_DST0 + SCAN_CHUNK - 1) / SCAN_CHUNK)   // 13
#define NBLK1 ((N_DST1 + SCAN_CHUNK - 1) / SCAN_CHUNK)   // 3
#define NBLKS (NBLK0 + NBLK1)                            // 16

#define NEDGE_BLK ((NE0 + NE1 + 255) / 256)              // 3750
#define NCVT_TOT  ((N_SRC0 * (DIM / 8)) / 256)           // 25000 (8 floats/thr)
#define NCVT_H    (NCVT_TOT / 2)                         // 12500

// ---------------------------------------------------------------------------
// Scratch
// ---------------------------------------------------------------------------
__device__ __align__(16) __half g_agg0h[(size_t)N_DST0 * DIM];
__device__ __align__(16) __half g_agg1h[(size_t)N_DST1 * DIM];
__device__ __align__(16) __half g_h0h[(size_t)N_DST0 * DIM];
__device__ float  g_h1[(size_t)N_DST1 * DIM];
__device__ __align__(16) __half g_xh[(size_t)N_SRC0 * DIM];

// fp16 weights (converted once per call in zero_kernel)
__device__ __align__(16) __half g_lw0h[DIM * DIM];
__device__ __align__(16) __half g_lw1h[DIM * DIM];
__device__ __align__(16) __half g_w0h[NBASE * BD * BD];
__device__ __align__(16) __half g_w1h[NBASE * BD * BD];

__device__ __align__(16) int g_cnt0[N_DST0];
__device__ __align__(16) int g_cnt1[N_DST1];
__device__ __align__(16) int g_rowptr0[N_DST0 + 1];
__device__ __align__(16) int g_rowptr1[N_DST1 + 1];
__device__ __align__(16) int g_cur0[N_DST0];
__device__ __align__(16) int g_cur1[N_DST1];
__device__ int g_esrc0[NE0];
__device__ int g_esrc1[NE1];
__device__ int g_part[NBLKS];
__device__ int g_flag[NBLKS];
__device__ int g_cnt_done;      // count blocks completed (for in-kernel scan)

// ---------------------------------------------------------------------------
// cp.async helpers
// ---------------------------------------------------------------------------
__device__ __forceinline__ void cp16(uint32_t dst, const void* src, int bytes) {
    asm volatile("cp.async.cg.shared.global [%0], [%1], 16, %2;\n"
                 :: "r"(dst), "l"(src), "r"(bytes));
}
__device__ __forceinline__ void cp_commit() {
    asm volatile("cp.async.commit_group;\n");
}
template <int N>
__device__ __forceinline__ void cp_wait() {
    asm volatile("cp.async.wait_group %0;\n" :: "n"(N));
}

// ---------------------------------------------------------------------------
// Convert helper: one block converts 256*8 floats (2 LDG.128 + 1 STG.128 /thr)
// ---------------------------------------------------------------------------
__device__ __forceinline__ void convert_block(const float* __restrict__ x,
                                              size_t blk) {
    size_t i = blk * 256 + threadIdx.x;
    const float4* x4 = (const float4*)x;
    float4 a = x4[2 * i];
    float4 b = x4[2 * i + 1];
    __half2 h0 = __floats2half2_rn(a.x, a.y);
    __half2 h1 = __floats2half2_rn(a.z, a.w);
    __half2 h2 = __floats2half2_rn(b.x, b.y);
    __half2 h3 = __floats2half2_rn(b.z, b.w);
    uint4 o;
    o.x = *(uint32_t*)&h0; o.y = *(uint32_t*)&h1;
    o.z = *(uint32_t*)&h2; o.w = *(uint32_t*)&h3;
    ((uint4*)g_xh)[i] = o;
}

// ---------------------------------------------------------------------------
// Zero counters + scan state, convert weights to fp16
// ---------------------------------------------------------------------------
__global__ void zero_kernel(const float* __restrict__ loop0,
                            const float* __restrict__ W0,
                            const float* __restrict__ loop1,
                            const float* __restrict__ W1) {
    int stride = gridDim.x * blockDim.x;
    int i0 = blockIdx.x * blockDim.x + threadIdx.x;
    for (int i = i0; i < N_DST0; i += stride) g_cnt0[i] = 0;
    for (int i = i0; i < N_DST1; i += stride) g_cnt1[i] = 0;
    if (i0 < NBLKS) g_flag[i0] = 0;
    if (i0 == 0) g_cnt_done = 0;
    for (int i = i0; i < DIM * DIM / 2; i += stride) {
        float2 v = ((const float2*)loop0)[i];
        ((__half2*)g_lw0h)[i] = __floats2half2_rn(v.x, v.y);
        float2 u = ((const float2*)loop1)[i];
        ((__half2*)g_lw1h)[i] = __floats2half2_rn(u.x, u.y);
    }
    for (int i = i0; i < NBASE * BD * BD / 2; i += stride) {
        float2 v = ((const float2*)W0)[i];
        ((__half2*)g_w0h)[i] = __floats2half2_rn(v.x, v.y);
        float2 u = ((const float2*)W1)[i];
        ((__half2*)g_w1h)[i] = __floats2half2_rn(u.x, u.y);
    }
}

// ---------------------------------------------------------------------------
// Fused: edge counting (blocks [0, NEDGE_BLK)), scan (next NBLKS blocks,
// spinning until all count blocks signal completion), and the first half of
// the x conversion (remaining blocks). Scan runs under the convert stream.
// Count blocks have the lowest bids -> always scheduled/retired before the
// spinners starve anything (no circular wait).
// ---------------------------------------------------------------------------
__global__ __launch_bounds__(256) void count_scan_convert_kernel(
    const float* __restrict__ x,
    const int*   __restrict__ dst0,
    const int*   __restrict__ dst1)
{
    int bid = blockIdx.x;
    if (bid < NEDGE_BLK) {
        // ---- count ----
        int e = bid * 256 + threadIdx.x;
        if (e < NE0)            atomicAdd(&g_cnt0[dst0[e]], 1);
        else if (e < NE0 + NE1) atomicAdd(&g_cnt1[dst1[e - NE0]], 1);
        __threadfence();
        __syncthreads();
        if (threadIdx.x == 0) atomicAdd(&g_cnt_done, 1);
        return;
    }
    if (bid < NEDGE_BLK + NBLKS) {
        // ---- scan (decoupled lookback), 256 threads x 16 elems ----
        int gb = bid - NEDGE_BLK;
        const int* cnt; int* rowptr; int* cur; int n, nblk, b, segbase;
        if (gb < NBLK0) {
            cnt = g_cnt0; rowptr = g_rowptr0; cur = g_cur0;
            n = N_DST0; nblk = NBLK0; b = gb; segbase = 0;
        } else {
            cnt = g_cnt1; rowptr = g_rowptr1; cur = g_cur1;
            n = N_DST1; nblk = NBLK1; b = gb - NBLK0; segbase = NBLK0;
        }

        // wait for all count blocks
        if (threadIdx.x == 0) {
            while (atomicAdd(&g_cnt_done, 0) != NEDGE_BLK) { __nanosleep(64); }
        }
        __syncthreads();
        __threadfence();

        __shared__ int wsum[8];
        __shared__ int s_off;
        const int tid  = threadIdx.x;
        const int lane = tid & 31;
        const int wid  = tid >> 5;            // 0..7
        const int idx0 = b * SCAN_CHUNK + tid * 16;

        int v[16];
        if (idx0 + 16 <= n) {
            #pragma unroll
            for (int q = 0; q < 4; ++q) {
                int4 a = *(const int4*)(cnt + idx0 + q * 4);
                v[q*4+0]=a.x; v[q*4+1]=a.y; v[q*4+2]=a.z; v[q*4+3]=a.w;
            }
        } else {
            #pragma unroll
            for (int j = 0; j < 16; ++j) v[j] = (idx0 + j < n) ? cnt[idx0 + j] : 0;
        }
        int incl[16]; int tot = 0;
        #pragma unroll
        for (int j = 0; j < 16; ++j) { tot += v[j]; incl[j] = tot; }

        int wincl = tot;
        #pragma unroll
        for (int o = 1; o < 32; o <<= 1) {
            int t = __shfl_up_sync(0xFFFFFFFFu, wincl, o);
            if (lane >= o) wincl += t;
        }
        if (lane == 31) wsum[wid] = wincl;
        __syncthreads();
        if (tid == 0) {
            int running = 0;
            #pragma unroll
            for (int w = 0; w < 8; ++w) { int t = wsum[w]; wsum[w] = running; running += t; }
            g_part[gb] = running;
            __threadfence();
            atomicExch(&g_flag[gb], 1);
            int off = 0;
            for (int k = segbase; k < gb; ++k) {
                while (atomicAdd(&g_flag[k], 0) == 0) { }
                off += *((volatile int*)&g_part[k]);
            }
            s_off = off;
        }
        __syncthreads();

        int off = s_off;
        int myexcl = off + wsum[wid] + (wincl - tot);
        if (idx0 + 16 <= n) {
            #pragma unroll
            for (int q = 0; q < 4; ++q) {
                int4 r = make_int4(myexcl + incl[q*4+0]-v[q*4+0],
                                   myexcl + incl[q*4+1]-v[q*4+1],
                                   myexcl + incl[q*4+2]-v[q*4+2],
                                   myexcl + incl[q*4+3]-v[q*4+3]);
                *(int4*)(rowptr + idx0 + q * 4) = r;
                *(int4*)(cur + idx0 + q * 4)    = r;
            }
        } else {
            #pragma unroll
            for (int j = 0; j < 16; ++j)
                if (idx0 + j < n) {
                    int e = myexcl + incl[j] - v[j];
                    rowptr[idx0 + j] = e;
                    cur[idx0 + j] = e;
                }
        }
        if (b == nblk - 1 && tid == 0) rowptr[n] = off + g_part[gb];
        return;
    }
    // ---- convert (first half) ----
    convert_block(x, (size_t)(bid - NEDGE_BLK - NBLKS));
}

// ---------------------------------------------------------------------------
// Fused: CSR fill + second half of x conversion
// ---------------------------------------------------------------------------
__global__ __launch_bounds__(256) void fill_convert_kernel(
    const float* __restrict__ x,
    const int* __restrict__ src0, const int* __restrict__ dst0,
    const int* __restrict__ src1, const int* __restrict__ dst1)
{
    int bid = blockIdx.x;
    if (bid < NEDGE_BLK) {
        int e = bid * 256 + threadIdx.x;
        if (e < NE0) {
            int p = atomicAdd(&g_cur0[dst0[e]], 1);
            g_esrc0[p] = src0[e];
        } else if (e < NE0 + NE1) {
            int e1 = e - NE0;
            int p = atomicAdd(&g_cur1[dst1[e1]], 1);
            g_esrc1[p] = src1[e1];
        }
    } else {
        convert_block(x, (size_t)(bid - NEDGE_BLK) + NCVT_H);
    }
}

// ---------------------------------------------------------------------------
// Pull gather (fp16 -> fp16 agg, fp32 accumulation). 32 threads/row,
// 4-edge unroll (proven round-12 form).
// ---------------------------------------------------------------------------
template <int WHICH>
__global__ __launch_bounds__(128) void gather_kernel() {
    const __half* feat = WHICH ? g_h0h : g_xh;
    __half* agg        = WHICH ? g_agg1h : g_agg0h;
    const int* rowptr  = WHICH ? g_rowptr1 : g_rowptr0;
    const int* esrc    = WHICH ? g_esrc1 : g_esrc0;
    const int ndst     = WHICH ? N_DST1 : N_DST0;

    int d = blockIdx.x * 4 + (threadIdx.x >> 5);
    int lane = threadIdx.x & 31;
    if (d >= ndst) return;

    int beg = rowptr[d], end = rowptr[d + 1];
    float a0=0.f,a1=0.f,a2=0.f,a3=0.f,a4=0.f,a5=0.f,a6=0.f,a7=0.f;
    const uint4* f16 = (const uint4*)feat;

    #define ACCUM(v) do {                                           \
        float2 _f;                                                  \
        _f = __half22float2(*(__half2*)&(v).x); a0 += _f.x; a1 += _f.y; \
        _f = __half22float2(*(__half2*)&(v).y); a2 += _f.x; a3 += _f.y; \
        _f = __half22float2(*(__half2*)&(v).z); a4 += _f.x; a5 += _f.y; \
        _f = __half22float2(*(__half2*)&(v).w); a6 += _f.x; a7 += _f.y; \
    } while (0)

    int i = beg;
    for (; i + 3 < end; i += 4) {
        int s0 = esrc[i], s1 = esrc[i + 1], s2 = esrc[i + 2], s3 = esrc[i + 3];
        uint4 v0 = f16[(size_t)s0 * 32 + lane];
        uint4 v1 = f16[(size_t)s1 * 32 + lane];
        uint4 v2 = f16[(size_t)s2 * 32 + lane];
        uint4 v3 = f16[(size_t)s3 * 32 + lane];
        ACCUM(v0); ACCUM(v1); ACCUM(v2); ACCUM(v3);
    }
    for (; i < end; ++i) {
        int s0 = esrc[i];
        uint4 v0 = f16[(size_t)s0 * 32 + lane];
        ACCUM(v0);
    }
    #undef ACCUM

    __half2 o0 = __floats2half2_rn(a0, a1);
    __half2 o1 = __floats2half2_rn(a2, a3);
    __half2 o2 = __floats2half2_rn(a4, a5);
    __half2 o3 = __floats2half2_rn(a6, a7);
    uint4 ov;
    ov.x = *(uint32_t*)&o0; ov.y = *(uint32_t*)&o1;
    ov.z = *(uint32_t*)&o2; ov.w = *(uint32_t*)&o3;
    ((uint4*)agg)[(size_t)d * 32 + lane] = ov;
}

// ---------------------------------------------------------------------------
// fp16 tensor-core fused layer GEMM, double-buffered cp.async pipeline.
// ---------------------------------------------------------------------------
__device__ __forceinline__ __half2 f2h2(float a, float b) {
    return __floats2half2_rn(a, b);
}

template <int LAYER>
__global__ __launch_bounds__(256) void layer_kernel(
    const float* __restrict__ bias,   // [256] fp32
    float*       __restrict__ out2,   // layer1: mirror to d_out region
    int M)
{
    const __half* aggh = (LAYER == 0) ? g_agg0h : g_agg1h;
    const __half* xdh  = (LAYER == 0) ? g_xh   : g_h0h;
    const __half* lw   = (LAYER == 0) ? g_lw0h : g_lw1h;
    const __half* wbd  = (LAYER == 0) ? g_w0h  : g_w1h;

    __shared__ __half As[2][128][40];
    __shared__ __half Bs[2][32][72];

    const int cb  = blockIdx.x;
    const int r0  = blockIdx.y * 128;
    const int tid = threadIdx.x;
    const int lane = tid & 31;
    const int w   = tid >> 5;
    const int wm  = w & 3;
    const int wn  = w >> 2;
    const int t4  = lane >> 2;
    const int tc  = lane & 3;

    const int arow0 = tid >> 2,         aq0 = tid & 3;
    const int arow1 = (tid + 256) >> 2, aq1 = (tid + 256) & 3;
    const int bk = tid >> 3, bq = tid & 7;
    uint32_t asA[2], asA2[2], asB[2];
    #pragma unroll
    for (int s = 0; s < 2; ++s) {
        asA[s]  = (uint32_t)__cvta_generic_to_shared(&As[s][arow0][aq0 * 8]);
        asA2[s] = (uint32_t)__cvta_generic_to_shared(&As[s][arow1][aq1 * 8]);
        asB[s]  = (uint32_t)__cvta_generic_to_shared(&Bs[s][bk][bq * 8]);
    }

    float acc[2][4][4];
    #pragma unroll
    for (int mt = 0; mt < 2; ++mt)
        #pragma unroll
        for (int nt = 0; nt < 4; ++nt)
            #pragma unroll
            for (int i = 0; i < 4; ++i) acc[mt][nt][i] = 0.f;

    auto issue = [&](int ch, int buf) {
        const int akbase = (ch < 8) ? ch * 32 : cb * 64 + (ch - 8) * 32;
        const __half* amat = (ch < 8) ? xdh : aggh;
        int r = r0 + arow0;
        cp16(asA[buf],
             amat + (size_t)(r < M ? r : 0) * DIM + akbase + aq0 * 8,
             r < M ? 16 : 0);
        r = r0 + arow1;
        cp16(asA2[buf],
             amat + (size_t)(r < M ? r : 0) * DIM + akbase + aq1 * 8,
             r < M ? 16 : 0);
        const __half* bsrc = (ch < 8)
            ? lw + (size_t)(ch * 32 + bk) * DIM + cb * 64 + bq * 8
            : wbd + (size_t)cb * BD * BD + (size_t)((ch - 8) * 32 + bk) * BD + bq * 8;
        cp16(asB[buf], bsrc, 16);
        cp_commit();
    };

    issue(0, 0);
    for (int ch = 0; ch < 10; ++ch) {
        const int buf = ch & 1;
        if (ch < 9) issue(ch + 1, buf ^ 1);
        if (ch < 9) cp_wait<1>(); else cp_wait<0>();
        __syncthreads();

        const __half (*A)[40] = As[buf];
        const __half (*B)[72] = Bs[buf];
        #pragma unroll
        for (int ks = 0; ks < 2; ++ks) {
            const int kb = ks * 16;
            uint32_t a[2][4];
            #pragma unroll
            for (int mt = 0; mt < 2; ++mt) {
                int mrow = wm * 32 + mt * 16 + t4;
                a[mt][0] = *(const uint32_t*)&A[mrow][kb + 2 * tc];
                a[mt][1] = *(const uint32_t*)&A[mrow + 8][kb + 2 * tc];
                a[mt][2] = *(const uint32_t*)&A[mrow][kb + 2 * tc + 8];
                a[mt][3] = *(const uint32_t*)&A[mrow + 8][kb + 2 * tc + 8];
            }
            #pragma unroll
            for (int nt = 0; nt < 4; ++nt) {
                int ncol = wn * 32 + nt * 8 + t4;
                uint32_t b0 = (uint32_t)*(const uint16_t*)&B[kb + 2 * tc][ncol]
                            | ((uint32_t)*(const uint16_t*)&B[kb + 2 * tc + 1][ncol] << 16);
                uint32_t b1 = (uint32_t)*(const uint16_t*)&B[kb + 2 * tc + 8][ncol]
                            | ((uint32_t)*(const uint16_t*)&B[kb + 2 * tc + 9][ncol] << 16);
                #pragma unroll
                for (int mt = 0; mt < 2; ++mt) {
                    asm volatile(
                        "mma.sync.aligned.m16n8k16.row.col.f32.f16.f16.f32 "
                        "{%0,%1,%2,%3}, {%4,%5,%6,%7}, {%8,%9}, {%0,%1,%2,%3};\n"
                        : "+f"(acc[mt][nt][0]), "+f"(acc[mt][nt][1]),
                          "+f"(acc[mt][nt][2]), "+f"(acc[mt][nt][3])
                        : "r"(a[mt][0]), "r"(a[mt][1]), "r"(a[mt][2]), "r"(a[mt][3]),
                          "r"(b0), "r"(b1));
                }
            }
        }
        __syncthreads();
    }

    #pragma unroll
    for (int nt = 0; nt < 4; ++nt) {
        int c = cb * 64 + wn * 32 + nt * 8 + 2 * tc;
        float2 bb = *(const float2*)(bias + c);
        #pragma unroll
        for (int mt = 0; mt < 2; ++mt) {
            int r = r0 + wm * 32 + mt * 16 + t4;
            float ox0 = fmaxf(acc[mt][nt][0] + bb.x, 0.f);
            float oy0 = fmaxf(acc[mt][nt][1] + bb.y, 0.f);
            float ox1 = fmaxf(acc[mt][nt][2] + bb.x, 0.f);
            float oy1 = fmaxf(acc[mt][nt][3] + bb.y, 0.f);
            if (LAYER == 0) {
                if (r < M)
                    *(__half2*)(g_h0h + (size_t)r * DIM + c) = f2h2(ox0, oy0);
                if (r + 8 < M)
                    *(__half2*)(g_h0h + (size_t)(r + 8) * DIM + c) = f2h2(ox1, oy1);
            } else {
                if (r < M) {
                    float2 o = make_float2(ox0, oy0);
                    *(float2*)(g_h1 + (size_t)r * DIM + c) = o;
                    *(float2*)(out2 + (size_t)r * DIM + c) = o;
                }
                if (r + 8 < M) {
                    float2 o = make_float2(ox1, oy1);
                    *(float2*)(g_h1 + (size_t)(r + 8) * DIM + c) = o;
                    *(float2*)(out2 + (size_t)(r + 8) * DIM + c) = o;
                }
            }
        }
    }
}

// ---------------------------------------------------------------------------
// Link predictor, batched: 32 pairs per 128-thread block.
// ---------------------------------------------------------------------------
#define PPB 32
__global__ __launch_bounds__(128) void pred_kernel(
    const int*   __restrict__ ps, const int* __restrict__ pd,
    const int*   __restrict__ ns, const int* __restrict__ nd,
    const float* __restrict__ pw1,
    const float* __restrict__ pb1,
    const float* __restrict__ pw2,
    const float* __restrict__ pb2,
    float*       __restrict__ out)
{
    const float* h = g_h1;
    __shared__ float es[PPB][256];
    __shared__ int   sa[PPB], sb[PPB];
    __shared__ float s_part[4][PPB];

    int tid  = threadIdx.x;
    int lane = tid & 31;
    int wid  = tid >> 5;
    int pbase = blockIdx.x * PPB;

    if (tid < PPB) {
        int P = pbase + tid;
        int a = 0, b = 0;
        if (P < NPTOT) {
            if (P < NPAIR) { a = ps[P]; b = pd[P]; }
            else           { a = ns[P - NPAIR]; b = nd[P - NPAIR]; }
        }
        sa[tid] = a; sb[tid] = b;
    }
    __syncthreads();

    #pragma unroll 4
    for (int p = 0; p < PPB; ++p) {
        int a = sa[p], b = sb[p];
        es[p][tid]       = h[(size_t)a * DIM + tid]       * h[(size_t)b * DIM + tid];
        es[p][tid + 128] = h[(size_t)a * DIM + 128 + tid] * h[(size_t)b * DIM + 128 + tid];
    }
    __syncthreads();

    float acc[PPB];
    #pragma unroll
    for (int p = 0; p < PPB; ++p) acc[p] = 0.f;

    for (int j = 0; j < 256; j += 4) {
        float w0 = pw1[(j + 0) * 128 + tid];
        float w1 = pw1[(j + 1) * 128 + tid];
        float w2 = pw1[(j + 2) * 128 + tid];
        float w3 = pw1[(j + 3) * 128 + tid];
        #pragma unroll
        for (int p = 0; p < PPB; ++p) {
            float4 e4 = *(const float4*)&es[p][j];
            acc[p] += e4.x * w0 + e4.y * w1 + e4.z * w2 + e4.w * w3;
        }
    }

    float pb  = pb1[tid];
    float w2v = pw2[tid];
    #pragma unroll
    for (int p = 0; p < PPB; ++p) {
        float v = fmaxf(acc[p] + pb, 0.f) * w2v;
        #pragma unroll
        for (int o = 16; o; o >>= 1) v += __shfl_xor_sync(0xFFFFFFFFu, v, o);
        if (lane == 0) s_part[wid][p] = v;
    }
    __syncthreads();
    if (tid < PPB) {
        int P = pbase + tid;
        if (P < NPTOT)
            out[P] = s_part[0][tid] + s_part[1][tid] + s_part[2][tid] + s_part[3][tid]
                   + pb2[0];
    }
}

// ---------------------------------------------------------------------------
// Launch
// ---------------------------------------------------------------------------
extern "C" void kernel_launch(void* const* d_in, const int* in_sizes, int n_in,
                              void* d_out, int out_size)
{
    const float* x     = (const float*)d_in[0];
    const int*   src0  = (const int*)d_in[1];
    const int*   dst0  = (const int*)d_in[2];
    const int*   src1  = (const int*)d_in[3];
    const int*   dst1  = (const int*)d_in[4];
    const int*   psrc  = (const int*)d_in[5];
    const int*   pdst  = (const int*)d_in[6];
    const int*   nsrc  = (const int*)d_in[7];
    const int*   ndst  = (const int*)d_in[8];
    const float* W0    = (const float*)d_in[9];
    const float* loop0 = (const float*)d_in[10];
    const float* b0    = (const float*)d_in[11];
    const float* W1    = (const float*)d_in[12];
    const float* loop1 = (const float*)d_in[13];
    const float* b1    = (const float*)d_in[14];
    const float* pw1   = (const float*)d_in[15];
    const float* pb1   = (const float*)d_in[16];
    const float* pw2   = (const float*)d_in[17];
    const float* pb2   = (const float*)d_in[18];
    float*       out   = (float*)d_out;

    // zero counters/flags + fp16 weight staging
    zero_kernel<<<256, 256>>>(loop0, W0, loop1, W1);
    // count + scan (in-kernel, after counts complete) + first convert half
    count_scan_convert_kernel<<<NEDGE_BLK + NBLKS + NCVT_H, 256>>>(x, dst0, dst1);
    // CSR fill + second convert half
    fill_convert_kernel<<<NEDGE_BLK + (NCVT_TOT - NCVT_H), 256>>>(
        x, src0, dst0, src1, dst1);

    // layer 0
    gather_kernel<0><<<(N_DST0 + 3) / 4, 128>>>();
    {
        dim3 grid(NBASE, (N_DST0 + 127) / 128);
        layer_kernel<0><<<grid, 256>>>(b0, nullptr, N_DST0);
    }

    // layer 1
    gather_kernel<1><<<(N_DST1 + 3) / 4, 128>>>();
    {
        dim3 grid(NBASE, (N_DST1 + 127) / 128);
        layer_kernel<1><<<grid, 256>>>(b1, out + NPTOT, N_DST1);
    }

    // link prediction
    pred_kernel<<<(NPTOT + PPB - 1) / PPB, 128>>>(psrc, pdst, nsrc, ndst,
                                                  pw1, pb1, pw2, pb2, out);
}